// round 13
// baseline (speedup 1.0000x reference)
#include <cuda_runtime.h>
#include <cuda_bf16.h>

// Persistent 2-layer tanh RNN, sm_103 tensor cores (mma.sync bf16 x3).
// R13: 2 grid barriers/step (was 4) and NO reduce phases.
//  - 64x64 CTA tiles, 4m x 16n x 2 k-splits = 128 CTAs
//  - ks=1 dumps fp32 partial + releases per-tile flag; ks=0 merges the partial
//    into its register accumulators, applies bias+tanh+split, writes h directly
//  - fc fold via M0 and batched output GEMM kept from R8/R12 (validated)

typedef unsigned long long u64;
typedef unsigned int u32;

namespace {
constexpr int NCTA = 128;
constexpr int NTHR = 256;
constexpr int Bm = 256, Hd = 1024, Ind = 256, Tt = 512;
constexpr int BmHd = Bm * Hd;
// double-buffered smem: per buffer 4 bf16 64x64 tiles (Ah, Al, Wh, Wl) x 8KB
constexpr int BUFB = 32768;
constexpr int T_AH = 0, T_AL = 8192, T_WH = 16384, T_WL = 24576;
constexpr int SMEM_BYTES = 2 * BUFB;  // 64KB
}

// ---- device-global state (allocation-free rule) ----
__device__ __align__(16) __nv_bfloat16 g_Wih0h[Hd * Ind], g_Wih0l[Hd * Ind];
__device__ __align__(16) __nv_bfloat16 g_Whh0h[Hd * Hd],  g_Whh0l[Hd * Hd];
__device__ __align__(16) __nv_bfloat16 g_Wih1h[Hd * Hd],  g_Wih1l[Hd * Hd];
__device__ __align__(16) __nv_bfloat16 g_Whh1h[Hd * Hd],  g_Whh1l[Hd * Hd];
__device__ __align__(16) __nv_bfloat16 g_M0h[Hd * Hd],    g_M0l[Hd * Hd];
__device__ __align__(16) __nv_bfloat16 g_fcWh[Ind * Hd],  g_fcWl[Ind * Hd];
__device__ __align__(16) __nv_bfloat16 g_fcWTh[Hd * Ind], g_fcWTl[Hd * Ind];
__device__ __align__(16) __nv_bfloat16 g_yh[Bm * Ind],    g_yl[Bm * Ind];
__device__ __align__(16) __nv_bfloat16 g_h0h[2][BmHd],    g_h0l[2][BmHd];
__device__ __align__(16) __nv_bfloat16 g_H1h[Tt * BmHd],  g_H1l[Tt * BmHd];
__device__ float g_biasA1[Hd], g_biasAf[Hd], g_biasB[Hd];
__device__ float g_part[64 * 4096];   // per-tile 64x64 fp32 partial (ks=1 -> ks=0)
__device__ u32 g_flag[64];            // per-tile monotonic phase token
__device__ unsigned g_arrive = 0, g_gen = 0;

// ---- helpers ----
__device__ __forceinline__ u32 smem_u32(const void *p) {
    u32 a;
    asm("{ .reg .u64 t; cvta.to.shared.u64 t, %1; cvt.u32.u64 %0, t; }"
        : "=r"(a) : "l"(p));
    return a;
}

#define LDMX4(r, a) \
    asm volatile("ldmatrix.sync.aligned.m8n8.x4.shared.b16 {%0,%1,%2,%3}, [%4];" \
                 : "=r"((r)[0]), "=r"((r)[1]), "=r"((r)[2]), "=r"((r)[3]) : "r"(a))

__device__ __forceinline__ void mma16816(float *c, const u32 *a, u32 b0, u32 b1) {
    asm volatile(
        "mma.sync.aligned.m16n8k16.row.col.f32.bf16.bf16.f32 "
        "{%0,%1,%2,%3}, {%4,%5,%6,%7}, {%8,%9}, {%0,%1,%2,%3};"
        : "+f"(c[0]), "+f"(c[1]), "+f"(c[2]), "+f"(c[3])
        : "r"(a[0]), "r"(a[1]), "r"(a[2]), "r"(a[3]), "r"(b0), "r"(b1));
}

__device__ __forceinline__ void commitg() {
    asm volatile("cp.async.commit_group;" ::: "memory");
}
__device__ __forceinline__ void waitg0() {
    asm volatile("cp.async.wait_group 0;" ::: "memory");
}
__device__ __forceinline__ void waitg1() {
    asm volatile("cp.async.wait_group 1;" ::: "memory");
}

// ---- grid barrier (validated R4-R12) ----
__device__ __forceinline__ void grid_sync() {
    __syncthreads();
    if (threadIdx.x == 0) {
        unsigned gen = *(volatile unsigned *)&g_gen;
        __threadfence();
        if (atomicAdd(&g_arrive, 1u) == NCTA - 1) {
            atomicExch(&g_arrive, 0u);
            __threadfence();
            atomicAdd(&g_gen, 1u);
        } else {
            while (*(volatile unsigned *)&g_gen == gen) { }
            __threadfence();
        }
    }
    __syncthreads();
}

// pairwise flag sync (same fence+atomic pattern as grid_sync)
__device__ __forceinline__ void flag_release(int tile, u32 c) {
    __syncthreads();
    if (threadIdx.x == 0) {
        __threadfence();
        atomicExch(&g_flag[tile], c);
    }
}
__device__ __forceinline__ void flag_wait(int tile, u32 c) {
    if (threadIdx.x == 0) {
        while (*(volatile u32 *)&g_flag[tile] < c) { }
        __threadfence();
    }
    __syncthreads();
}

__device__ __forceinline__ void split_bf16(float v, __nv_bfloat16 &h, __nv_bfloat16 &l) {
    h = __float2bfloat16(v);
    l = __float2bfloat16(v - __bfloat162float(h));
}

// cp.async one 64x64 bf16 tile (128B rows, SW128 xor swizzle) into smem.
__device__ __forceinline__ void stage_async(u32 sdst, const __nv_bfloat16 *g,
                                            int ld, int kb) {
    const int tid = threadIdx.x;
#pragma unroll
    for (int j = 0; j < 2; ++j) {
        const int u = tid + NTHR * j;
        const int row = u >> 3, blk = u & 7;
        const size_t src = __cvta_generic_to_global(&g[(long)row * ld + kb + blk * 8]);
        const u32 dst = sdst + row * 128 + ((blk ^ (row & 7)) << 4);
        asm volatile("cp.async.cg.shared.global [%0], [%1], 16;"
                     :: "r"(dst), "l"(src) : "memory");
    }
}

__device__ __forceinline__ void issue_chunk(
    u32 sbuf, const __nv_bfloat16 *Ah, const __nv_bfloat16 *Al, int lda,
    const __nv_bfloat16 *Wh, const __nv_bfloat16 *Wl, int ldw, int kb) {
    stage_async(sbuf + T_AH, Ah, lda, kb);
    stage_async(sbuf + T_AL, Al, lda, kb);
    stage_async(sbuf + T_WH, Wh, ldw, kb);
    stage_async(sbuf + T_WL, Wl, ldw, kb);
    commitg();
}

// MMA over one 64-k chunk of a 64x64 tile. 8 warps as 2m x 4n; warp tile 32x16
// (2 m-atoms x 2 n-atoms). 3 precision passes: ah*bh + ah*bl + al*bh.
__device__ __forceinline__ void mma_tile(float (&acc)[2][2][4], u32 sbase) {
    const int lid = threadIdx.x & 31, wid = threadIdx.x >> 5;
    const int wm = wid >> 2, wn = wid & 3;
    const int rA0 = wm * 32 + (lid & 7) + ((lid >> 3) & 1) * 8;
    const int cAsel = (lid >> 4) & 1;
    const int rB0 = wn * 16 + (lid & 7) + ((lid >> 4) & 1) * 8;
    const int cBsel = (lid >> 3) & 1;
#pragma unroll
    for (int k16 = 0; k16 < 4; ++k16) {
        u32 ah[2][4], al[2][4], bh[4], bl[4];
#pragma unroll
        for (int ma = 0; ma < 2; ++ma) {
            const int r = rA0 + ma * 16;
            const u32 off = (u32)(r * 128 + (((k16 * 2 + cAsel) ^ (r & 7)) << 4));
            LDMX4(ah[ma], sbase + T_AH + off);
            LDMX4(al[ma], sbase + T_AL + off);
        }
        {
            const int r = rB0;
            const u32 off = (u32)(r * 128 + (((k16 * 2 + cBsel) ^ (r & 7)) << 4));
            LDMX4(bh, sbase + T_WH + off);
            LDMX4(bl, sbase + T_WL + off);
        }
#pragma unroll
        for (int ma = 0; ma < 2; ++ma)
#pragma unroll
            for (int na = 0; na < 2; ++na) {
                const int q = na * 2;
                mma16816(acc[ma][na], ah[ma], bh[q], bh[q + 1]);
                mma16816(acc[ma][na], ah[ma], bl[q], bl[q + 1]);
                mma16816(acc[ma][na], al[ma], bh[q], bh[q + 1]);
            }
    }
}

// Double-buffered pipelined GEMM over nch 64-k chunks starting at kb.
__device__ __forceinline__ void gemm_pipe(
    float (&acc)[2][2][4], u32 sb,
    const __nv_bfloat16 *Ah, const __nv_bfloat16 *Al, int lda,
    const __nv_bfloat16 *Wh, const __nv_bfloat16 *Wl, int ldw,
    int kb, int nch)
{
    issue_chunk(sb, Ah, Al, lda, Wh, Wl, ldw, kb);
    if (nch > 1) issue_chunk(sb + BUFB, Ah, Al, lda, Wh, Wl, ldw, kb + 64);
    for (int i = 0; i < nch; ++i) {
        if (i + 1 < nch) waitg1(); else waitg0();
        __syncthreads();
        mma_tile(acc, sb + (u32)((i & 1) * BUFB));
        __syncthreads();
        if (i + 2 < nch)
            issue_chunk(sb + (u32)((i & 1) * BUFB), Ah, Al, lda, Wh, Wl, ldw,
                        kb + 64 * (i + 2));
    }
}

// Dump 64x64 fp32 tile (local coords) to the pairwise partial buffer.
__device__ __forceinline__ void dump_part(const float (&acc)[2][2][4],
                                          float *__restrict__ dst)
{
    const int lid = threadIdx.x & 31, wid = threadIdx.x >> 5;
    const int wm = wid >> 2, wn = wid & 3;
    const int g = lid >> 2, t = lid & 3;
#pragma unroll
    for (int ma = 0; ma < 2; ++ma)
#pragma unroll
        for (int na = 0; na < 2; ++na) {
            const int r = wm * 32 + ma * 16 + g;
            const int c = wn * 16 + na * 8 + t * 2;
            *reinterpret_cast<float2 *>(&dst[r * 64 + c]) =
                make_float2(acc[ma][na][0], acc[ma][na][1]);
            *reinterpret_cast<float2 *>(&dst[(r + 8) * 64 + c]) =
                make_float2(acc[ma][na][2], acc[ma][na][3]);
        }
}

// ks=0 epilogue: (+ partner partial) + bias, tanh, split, write bf16 h tile.
__device__ __forceinline__ void epi_h(
    float (&acc)[2][2][4], bool haspart, const float *__restrict__ part,
    const float *__restrict__ bias, int m0, int n0,
    __nv_bfloat16 *__restrict__ dh, __nv_bfloat16 *__restrict__ dl)
{
    const int lid = threadIdx.x & 31, wid = threadIdx.x >> 5;
    const int wm = wid >> 2, wn = wid & 3;
    const int g = lid >> 2, t = lid & 3;
#pragma unroll
    for (int ma = 0; ma < 2; ++ma)
#pragma unroll
        for (int na = 0; na < 2; ++na) {
            const int r = wm * 32 + ma * 16 + g;
            const int c = wn * 16 + na * 8 + t * 2;
            float2 v0 = make_float2(acc[ma][na][0], acc[ma][na][1]);
            float2 v1 = make_float2(acc[ma][na][2], acc[ma][na][3]);
            if (haspart) {
                const float2 p0 = __ldcg(reinterpret_cast<const float2 *>(&part[r * 64 + c]));
                const float2 p1 = __ldcg(reinterpret_cast<const float2 *>(&part[(r + 8) * 64 + c]));
                v0.x += p0.x; v0.y += p0.y; v1.x += p1.x; v1.y += p1.y;
            }
            const float bx = bias[n0 + c], by = bias[n0 + c + 1];
            const float o00 = tanhf(v0.x + bx), o01 = tanhf(v0.y + by);
            const float o10 = tanhf(v1.x + bx), o11 = tanhf(v1.y + by);
            __nv_bfloat16 h0, l0, h1, l1;
            const long i0 = (long)(m0 + r) * Hd + n0 + c;
            const long i1 = (long)(m0 + r + 8) * Hd + n0 + c;
            split_bf16(o00, h0, l0); split_bf16(o01, h1, l1);
            *reinterpret_cast<__nv_bfloat162 *>(&dh[i0]) = __halves2bfloat162(h0, h1);
            *reinterpret_cast<__nv_bfloat162 *>(&dl[i0]) = __halves2bfloat162(l0, l1);
            split_bf16(o10, h0, l0); split_bf16(o11, h1, l1);
            *reinterpret_cast<__nv_bfloat162 *>(&dh[i1]) = __halves2bfloat162(h0, h1);
            *reinterpret_cast<__nv_bfloat162 *>(&dl[i1]) = __halves2bfloat162(l0, l1);
        }
}

// M0 epilogue: split fp32 tile straight to bf16 hi/lo (no tanh/bias).
__device__ __forceinline__ void epi_M0(const float (&acc)[2][2][4], int m0, int n0) {
    const int lid = threadIdx.x & 31, wid = threadIdx.x >> 5;
    const int wm = wid >> 2, wn = wid & 3;
    const int g = lid >> 2, t = lid & 3;
#pragma unroll
    for (int ma = 0; ma < 2; ++ma)
#pragma unroll
        for (int na = 0; na < 2; ++na) {
            const int r = wm * 32 + ma * 16 + g;
            const int c = wn * 16 + na * 8 + t * 2;
            const long i0 = (long)(m0 + r) * Hd + n0 + c;
            const long i1 = (long)(m0 + r + 8) * Hd + n0 + c;
            split_bf16(acc[ma][na][0], g_M0h[i0], g_M0l[i0]);
            split_bf16(acc[ma][na][1], g_M0h[i0 + 1], g_M0l[i0 + 1]);
            split_bf16(acc[ma][na][2], g_M0h[i1], g_M0l[i1]);
            split_bf16(acc[ma][na][3], g_M0h[i1 + 1], g_M0l[i1 + 1]);
        }
}

// Final-GEMM epilogue: out[:, s, :] tile = acc + fc_b.
__device__ __forceinline__ void epi_out(
    const float (&acc)[2][2][4], float *__restrict__ out,
    const float *__restrict__ fc_b, int s, int m0, int n0)
{
    const int lid = threadIdx.x & 31, wid = threadIdx.x >> 5;
    const int wm = wid >> 2, wn = wid & 3;
    const int g = lid >> 2, t = lid & 3;
#pragma unroll
    for (int ma = 0; ma < 2; ++ma)
#pragma unroll
        for (int na = 0; na < 2; ++na) {
            const int r = m0 + wm * 32 + ma * 16 + g;
            const int c = n0 + wn * 16 + na * 8 + t * 2;
            const float bx = fc_b[c], by = fc_b[c + 1];
            *reinterpret_cast<float2 *>(&out[(long)r * (Tt * Ind) + (long)s * Ind + c]) =
                make_float2(acc[ma][na][0] + bx, acc[ma][na][1] + by);
            *reinterpret_cast<float2 *>(&out[(long)(r + 8) * (Tt * Ind) + (long)s * Ind + c]) =
                make_float2(acc[ma][na][2] + bx, acc[ma][na][3] + by);
        }
}

__device__ __forceinline__ void convert_split(
    const float *__restrict__ s, __nv_bfloat16 *dh, __nv_bfloat16 *dl, int n, int gtid)
{
    for (int i = gtid; i < n; i += NCTA * NTHR) split_bf16(s[i], dh[i], dl[i]);
}

__global__ void __launch_bounds__(NTHR, 1) rnn_tc(
    const float *__restrict__ y0,
    const float *__restrict__ W_ih0, const float *__restrict__ W_hh0,
    const float *__restrict__ b_ih0, const float *__restrict__ b_hh0,
    const float *__restrict__ W_ih1, const float *__restrict__ W_hh1,
    const float *__restrict__ b_ih1, const float *__restrict__ b_hh1,
    const float *__restrict__ fc_W, const float *__restrict__ fc_b,
    float *__restrict__ out)
{
    extern __shared__ char smem[];
    const u32 sb = smem_u32(smem);
    const int tid = threadIdx.x, bid = blockIdx.x;
    const int gtid = bid * NTHR + tid;
    const int stride = NCTA * NTHR;

    // ---- phase 0a (every replay): splits, transpose, init, biases, flags
    convert_split(W_ih0, g_Wih0h, g_Wih0l, Hd * Ind, gtid);
    convert_split(W_hh0, g_Whh0h, g_Whh0l, Hd * Hd, gtid);
    convert_split(W_ih1, g_Wih1h, g_Wih1l, Hd * Hd, gtid);
    convert_split(W_hh1, g_Whh1h, g_Whh1l, Hd * Hd, gtid);
    convert_split(fc_W, g_fcWh, g_fcWl, Ind * Hd, gtid);
    for (int i = gtid; i < Hd * Ind; i += stride) {  // fcWT[j][k] = fc_W[k][j]
        const int j = i >> 8, k = i & 255;
        split_bf16(fc_W[(long)k * Hd + j], g_fcWTh[i], g_fcWTl[i]);
    }
    for (int i = gtid; i < Bm * Ind; i += stride) {
        const float v = y0[i];
        split_bf16(v, g_yh[i], g_yl[i]);
        out[(long)(i >> 8) * (Tt * Ind) + (i & 255)] = v;  // out[:, 0, :]
    }
    for (int i = gtid; i < BmHd; i += stride) {
        const __nv_bfloat16 z = __float2bfloat16(0.0f);
        g_H1h[i] = z; g_H1l[i] = z;       // history slot 0 = h1 initial state
    }
    for (int j = gtid; j < Hd; j += stride) {
        const float s1 = b_ih0[j] + b_hh0[j];
        g_biasA1[j] = s1;
        float a = 0.0f;
        const float *wr = &W_ih0[(long)j * Ind];
        for (int k = 0; k < Ind; ++k) a += wr[k] * fc_b[k];
        g_biasAf[j] = a + s1;              // fc_b @ W_ih0^T + b_ih0 + b_hh0
        g_biasB[j] = b_ih1[j] + b_hh1[j];
    }
    if (gtid < 64) g_flag[gtid] = 0;       // reset pairwise tokens each replay
    grid_sync();

    // ---- phase 0b: M0 = W_ih0 @ fc_W (1024x1024, K=256); 256 tiles, 2 per CTA
    for (int j = bid * 2; j < bid * 2 + 2; ++j) {
        const int tm = j >> 4, tn = j & 15;
        float acc[2][2][4] = {};
        gemm_pipe(acc, sb,
                  g_Wih0h + (long)tm * 64 * Ind, g_Wih0l + (long)tm * 64 * Ind, Ind,
                  g_fcWTh + (long)tn * 64 * Ind, g_fcWTl + (long)tn * 64 * Ind, Ind,
                  0, 4);
        epi_M0(acc, tm * 64, tn * 64);
    }
    grid_sync();

    // tile mapping: 2 k-splits x (4m x 16n) of 64x64 over [256, 1024]
    const int ks = bid >> 6, tile = bid & 63;
    const int m0 = (tile >> 4) * 64, n0 = (tile & 15) * 64;
    float *mypart = g_part + tile * 4096;

    for (int s = 1; s < Tt; ++s) {
        const int cb = (s - 1) & 1, nb = s & 1;
        const u32 cA = (u32)(2 * s - 1), cB = (u32)(2 * s);
        const __nv_bfloat16 *h1ph = g_H1h + (long)(s - 1) * BmHd;
        const __nv_bfloat16 *h1pl = g_H1l + (long)(s - 1) * BmHd;

        // ---- stage A: h0(s) = tanh(h1(s-1)@M0^T + h0(s-1)@Whh0^T + biasAf)
        {
            float acc[2][2][4] = {};
            if (s == 1) {
                // h0(1) = tanh(y0 @ Wih0^T + biasA1); ks=1 half is zero
                if (ks == 0) {
                    gemm_pipe(acc, sb,
                              g_yh + (long)m0 * Ind, g_yl + (long)m0 * Ind, Ind,
                              g_Wih0h + (long)n0 * Ind, g_Wih0l + (long)n0 * Ind, Ind,
                              0, 4);
                    epi_h(acc, false, mypart, g_biasA1, m0, n0, g_h0h[nb], g_h0l[nb]);
                }
            } else if (ks == 1) {
                gemm_pipe(acc, sb,
                          g_h0h[cb] + (long)m0 * Hd, g_h0l[cb] + (long)m0 * Hd, Hd,
                          g_Whh0h + (long)n0 * Hd, g_Whh0l + (long)n0 * Hd, Hd,
                          0, 16);
                dump_part(acc, mypart);
                flag_release(tile, cA);
            } else {
                gemm_pipe(acc, sb,
                          h1ph + (long)m0 * Hd, h1pl + (long)m0 * Hd, Hd,
                          g_M0h + (long)n0 * Hd, g_M0l + (long)n0 * Hd, Hd,
                          0, 16);
                flag_wait(tile, cA);
                epi_h(acc, true, mypart, g_biasAf, m0, n0, g_h0h[nb], g_h0l[nb]);
            }
        }
        grid_sync();

        // ---- stage B: h1(s) = tanh(h0(s)@Wih1^T + h1(s-1)@Whh1^T + biasB)
        {
            float acc[2][2][4] = {};
            if (ks == 1) {
                gemm_pipe(acc, sb,
                          h1ph + (long)m0 * Hd, h1pl + (long)m0 * Hd, Hd,
                          g_Whh1h + (long)n0 * Hd, g_Whh1l + (long)n0 * Hd, Hd,
                          0, 16);
                dump_part(acc, mypart);
                flag_release(tile, cB);
            } else {
                gemm_pipe(acc, sb,
                          g_h0h[nb] + (long)m0 * Hd, g_h0l[nb] + (long)m0 * Hd, Hd,
                          g_Wih1h + (long)n0 * Hd, g_Wih1l + (long)n0 * Hd, Hd,
                          0, 16);
                flag_wait(tile, cB);
                epi_h(acc, true, mypart, g_biasB, m0, n0,
                      g_H1h + (long)s * BmHd, g_H1l + (long)s * BmHd);
            }
        }
        grid_sync();
    }

    // ---- batched output GEMM: out[:, s, :] = H1[s] @ fc_W^T + fc_b, s = 1..511
    // jobs: 511 steps x 4m x 4n tiles of 64x64; K=1024 full per job
    for (int job = bid; job < (Tt - 1) * 16; job += NCTA) {
        const int s = 1 + (job >> 4);
        const int t = job & 15;
        const int fm0 = (t >> 2) * 64, fn0 = (t & 3) * 64;
        float acc[2][2][4] = {};
        gemm_pipe(acc, sb,
                  g_H1h + (long)s * BmHd + (long)fm0 * Hd,
                  g_H1l + (long)s * BmHd + (long)fm0 * Hd, Hd,
                  g_fcWh + (long)fn0 * Hd, g_fcWl + (long)fn0 * Hd, Hd,
                  0, 16);
        epi_out(acc, out, fc_b, s, fm0, fn0);
    }
}

extern "C" void kernel_launch(void *const *d_in, const int *in_sizes, int n_in,
                              void *d_out, int out_size) {
    (void)in_sizes; (void)n_in; (void)out_size;
    const float *y0    = (const float *)d_in[0];
    // d_in[1] = t (length only; unused)
    const float *W_ih0 = (const float *)d_in[2];
    const float *W_hh0 = (const float *)d_in[3];
    const float *b_ih0 = (const float *)d_in[4];
    const float *b_hh0 = (const float *)d_in[5];
    const float *W_ih1 = (const float *)d_in[6];
    const float *W_hh1 = (const float *)d_in[7];
    const float *b_ih1 = (const float *)d_in[8];
    const float *b_hh1 = (const float *)d_in[9];
    const float *fc_W  = (const float *)d_in[10];
    const float *fc_b  = (const float *)d_in[11];
    float *out = (float *)d_out;

    cudaFuncSetAttribute(rnn_tc, cudaFuncAttributeMaxDynamicSharedMemorySize, SMEM_BYTES);
    rnn_tc<<<NCTA, NTHR, SMEM_BYTES>>>(y0, W_ih0, W_hh0, b_ih0, b_hh0,
                                       W_ih1, W_hh1, b_ih1, b_hh1,
                                       fc_W, fc_b, out);
}

// round 14
// speedup vs baseline: 1.1169x; 1.1169x over previous
#include <cuda_runtime.h>
#include <cuda_bf16.h>

// Persistent 2-layer tanh RNN, sm_103 tensor cores (mma.sync bf16 x3).
// R14 = R8 GEMM byte-identical (128 CTAs, 128x128 tiles, 8 warps 2x4, 8-way
// split-K, fc folded via M0, batched output GEMM) + sync restructure ONLY:
//   2 grid barriers/step (was 4). Reduce is folded into each stage: the 8 CTAs
//   of a tile sync on a per-tile arrival counter, then each merges a disjoint
//   16-row slice of the 8 partials (same volume & summation order as R8's
//   reduce) and writes h directly. R13's tile shrink (the confound) reverted.

typedef unsigned long long u64;
typedef unsigned int u32;

namespace {
constexpr int NCTA = 128;
constexpr int NTHR = 256;
constexpr int Bm = 256, Hd = 1024, Ind = 256, Tt = 512;
constexpr int BmHd = Bm * Hd;
// double-buffered dynamic smem: per buffer 4 bf16 tiles (Ah, Al, Wh, Wl) x 16KB
constexpr int BUFB = 65536;
constexpr int T_AH = 0, T_AL = 16384, T_WH = 32768, T_WL = 49152;
constexpr int SMEM_BYTES = 2 * BUFB;  // 128KB
constexpr int TILE_F = 128 * 128;     // floats per partial tile
}

// ---- device-global state (allocation-free rule) ----
__device__ __align__(16) __nv_bfloat16 g_Wih0h[Hd * Ind], g_Wih0l[Hd * Ind];
__device__ __align__(16) __nv_bfloat16 g_Whh0h[Hd * Hd],  g_Whh0l[Hd * Hd];
__device__ __align__(16) __nv_bfloat16 g_Wih1h[Hd * Hd],  g_Wih1l[Hd * Hd];
__device__ __align__(16) __nv_bfloat16 g_Whh1h[Hd * Hd],  g_Whh1l[Hd * Hd];
__device__ __align__(16) __nv_bfloat16 g_M0h[Hd * Hd],    g_M0l[Hd * Hd];
__device__ __align__(16) __nv_bfloat16 g_fcWh[Ind * Hd],  g_fcWl[Ind * Hd];
__device__ __align__(16) __nv_bfloat16 g_fcWTh[Hd * Ind], g_fcWTl[Hd * Ind];
__device__ __align__(16) __nv_bfloat16 g_yh[Bm * Ind],    g_yl[Bm * Ind];
__device__ __align__(16) __nv_bfloat16 g_h0h[2][BmHd],    g_h0l[2][BmHd];
__device__ __align__(16) __nv_bfloat16 g_H1h[Tt * BmHd],  g_H1l[Tt * BmHd];
__device__ float g_biasA1[Hd], g_biasAf[Hd], g_biasB[Hd];
// per-tile partials: 16 tiles x 8 ks x 128x128 fp32 (also M0 scratch in [0..1])
__device__ float g_part[16 * 8 * TILE_F];
__device__ u32 g_tcnt[16];            // per-tile monotonic arrival counter
__device__ unsigned g_arrive = 0, g_gen = 0;

// ---- helpers ----
__device__ __forceinline__ u32 smem_u32(const void *p) {
    u32 a;
    asm("{ .reg .u64 t; cvta.to.shared.u64 t, %1; cvt.u32.u64 %0, t; }"
        : "=r"(a) : "l"(p));
    return a;
}

#define LDMX4(r, a) \
    asm volatile("ldmatrix.sync.aligned.m8n8.x4.shared.b16 {%0,%1,%2,%3}, [%4];" \
                 : "=r"((r)[0]), "=r"((r)[1]), "=r"((r)[2]), "=r"((r)[3]) : "r"(a))

__device__ __forceinline__ void mma16816(float *c, const u32 *a, u32 b0, u32 b1) {
    asm volatile(
        "mma.sync.aligned.m16n8k16.row.col.f32.bf16.bf16.f32 "
        "{%0,%1,%2,%3}, {%4,%5,%6,%7}, {%8,%9}, {%0,%1,%2,%3};"
        : "+f"(c[0]), "+f"(c[1]), "+f"(c[2]), "+f"(c[3])
        : "r"(a[0]), "r"(a[1]), "r"(a[2]), "r"(a[3]), "r"(b0), "r"(b1));
}

__device__ __forceinline__ void commitg() {
    asm volatile("cp.async.commit_group;" ::: "memory");
}
__device__ __forceinline__ void waitg0() {
    asm volatile("cp.async.wait_group 0;" ::: "memory");
}
__device__ __forceinline__ void waitg1() {
    asm volatile("cp.async.wait_group 1;" ::: "memory");
}

// ---- grid barrier (validated R4-R13) ----
__device__ __forceinline__ void grid_sync() {
    __syncthreads();
    if (threadIdx.x == 0) {
        unsigned gen = *(volatile unsigned *)&g_gen;
        __threadfence();
        if (atomicAdd(&g_arrive, 1u) == NCTA - 1) {
            atomicExch(&g_arrive, 0u);
            __threadfence();
            atomicAdd(&g_gen, 1u);
        } else {
            while (*(volatile unsigned *)&g_gen == gen) { }
            __threadfence();
        }
    }
    __syncthreads();
}

// per-tile sub-barrier: producers arrive (monotonic count), all wait for target
__device__ __forceinline__ void tile_sync(int tile, bool produce, u32 target) {
    __syncthreads();
    if (threadIdx.x == 0) {
        if (produce) {
            __threadfence();
            atomicAdd(&g_tcnt[tile], 1u);
        }
        while (*(volatile u32 *)&g_tcnt[tile] < target) { }
        __threadfence();
    }
    __syncthreads();
}

__device__ __forceinline__ void split_bf16(float v, __nv_bfloat16 &h, __nv_bfloat16 &l) {
    h = __float2bfloat16(v);
    l = __float2bfloat16(v - __bfloat162float(h));
}

// cp.async one 128x64 bf16 tile (SW128 xor swizzle) into smem.
__device__ __forceinline__ void stage_async(u32 sdst, const __nv_bfloat16 *g,
                                            int ld, int kb) {
    const int tid = threadIdx.x;
#pragma unroll
    for (int j = 0; j < 4; ++j) {
        const int u = tid + NTHR * j;
        const int row = u >> 3, blk = u & 7;
        const size_t src = __cvta_generic_to_global(&g[(long)row * ld + kb + blk * 8]);
        const u32 dst = sdst + row * 128 + ((blk ^ (row & 7)) << 4);
        asm volatile("cp.async.cg.shared.global [%0], [%1], 16;"
                     :: "r"(dst), "l"(src) : "memory");
    }
}

__device__ __forceinline__ void issue_chunk(
    u32 sbuf, const __nv_bfloat16 *Ah, const __nv_bfloat16 *Al, int lda,
    const __nv_bfloat16 *Wh, const __nv_bfloat16 *Wl, int ldw, int kb) {
    stage_async(sbuf + T_AH, Ah, lda, kb);
    stage_async(sbuf + T_AL, Al, lda, kb);
    stage_async(sbuf + T_WH, Wh, ldw, kb);
    stage_async(sbuf + T_WL, Wl, ldw, kb);
    commitg();
}

// MMA over one staged 64-k chunk. 8 warps as 2x4; warp tile 64x32
// (4 m-atoms x 4 n-atoms). 3 precision passes: ah*bh + ah*bl + al*bh. (R8)
__device__ __forceinline__ void mma_tile(float (&acc)[4][4][4], u32 sbase) {
    const int lid = threadIdx.x & 31, wid = threadIdx.x >> 5;
    const int wm = wid >> 2, wn = wid & 3;
    const int rA0 = wm * 64 + (lid & 7) + ((lid >> 3) & 1) * 8;
    const int cAsel = (lid >> 4) & 1;
    const int rB0 = wn * 32 + (lid & 7) + ((lid >> 4) & 1) * 8;
    const int cBsel = (lid >> 3) & 1;
#pragma unroll
    for (int k16 = 0; k16 < 4; ++k16) {
        u32 ah[4][4], al[4][4], bh[2][4], bl[2][4];
#pragma unroll
        for (int ma = 0; ma < 4; ++ma) {
            const int r = rA0 + ma * 16;
            const u32 off = (u32)(r * 128 + (((k16 * 2 + cAsel) ^ (r & 7)) << 4));
            LDMX4(ah[ma], sbase + T_AH + off);
            LDMX4(al[ma], sbase + T_AL + off);
        }
#pragma unroll
        for (int p = 0; p < 2; ++p) {
            const int r = rB0 + p * 16;
            const u32 off = (u32)(r * 128 + (((k16 * 2 + cBsel) ^ (r & 7)) << 4));
            LDMX4(bh[p], sbase + T_WH + off);
            LDMX4(bl[p], sbase + T_WL + off);
        }
#pragma unroll
        for (int ma = 0; ma < 4; ++ma)
#pragma unroll
            for (int na = 0; na < 4; ++na) {
                const int p = na >> 1, q = (na & 1) * 2;
                mma16816(acc[ma][na], ah[ma], bh[p][q], bh[p][q + 1]);
                mma16816(acc[ma][na], ah[ma], bl[p][q], bl[p][q + 1]);
                mma16816(acc[ma][na], al[ma], bh[p][q], bh[p][q + 1]);
            }
    }
}

// Double-buffered pipelined GEMM over nch 64-k chunks starting at kb (R8).
__device__ __forceinline__ void gemm_pipe(
    float (&acc)[4][4][4], u32 sb,
    const __nv_bfloat16 *Ah, const __nv_bfloat16 *Al, int lda,
    const __nv_bfloat16 *Wh, const __nv_bfloat16 *Wl, int ldw,
    int kb, int nch)
{
    issue_chunk(sb, Ah, Al, lda, Wh, Wl, ldw, kb);
    if (nch > 1) issue_chunk(sb + BUFB, Ah, Al, lda, Wh, Wl, ldw, kb + 64);
    for (int i = 0; i < nch; ++i) {
        if (i + 1 < nch) waitg1(); else waitg0();
        __syncthreads();
        mma_tile(acc, sb + (u32)((i & 1) * BUFB));
        __syncthreads();
        if (i + 2 < nch)
            issue_chunk(sb + (u32)((i & 1) * BUFB), Ah, Al, lda, Wh, Wl, ldw,
                        kb + 64 * (i + 2));
    }
}

// Dump 128x128 fp32 accumulator tile (tile-local coords, ldc fixed 128).
__device__ __forceinline__ void dump_loc(const float (&acc)[4][4][4],
                                         float *__restrict__ dst)
{
    const int lid = threadIdx.x & 31, wid = threadIdx.x >> 5;
    const int wm = wid >> 2, wn = wid & 3;
    const int g = lid >> 2, t = lid & 3;
#pragma unroll
    for (int ma = 0; ma < 4; ++ma)
#pragma unroll
        for (int na = 0; na < 4; ++na) {
            const int row = wm * 64 + ma * 16 + g;
            const int col = wn * 32 + na * 8 + t * 2;
            *reinterpret_cast<float2 *>(&dst[row * 128 + col]) =
                make_float2(acc[ma][na][0], acc[ma][na][1]);
            *reinterpret_cast<float2 *>(&dst[(row + 8) * 128 + col]) =
                make_float2(acc[ma][na][2], acc[ma][na][3]);
        }
}

// In-stage merge: this CTA (split myks) merges rows [myks*16, myks*16+16) of
// its tile: sum cnt partials + bias, tanh, bf16 hi/lo split, write h slice.
// Same per-CTA volume and summation order as R8's reduce_stage.
__device__ __forceinline__ void merge_h(
    const float *__restrict__ tbase, int myks, int cnt,
    const float *__restrict__ bias, int m0, int n0,
    __nv_bfloat16 *__restrict__ dh, __nv_bfloat16 *__restrict__ dl)
{
    const int t = threadIdx.x;
    const int row = myks * 16 + (t >> 4);
    const int c = (t & 15) * 8;
    const float *p = tbase + row * 128 + c;
    float4 a0 = __ldcg(reinterpret_cast<const float4 *>(p));
    float4 a1 = __ldcg(reinterpret_cast<const float4 *>(p + 4));
    for (int q = 1; q < cnt; ++q) {
        const float *pp = p + q * TILE_F;
        const float4 b0 = __ldcg(reinterpret_cast<const float4 *>(pp));
        const float4 b1 = __ldcg(reinterpret_cast<const float4 *>(pp + 4));
        a0.x += b0.x; a0.y += b0.y; a0.z += b0.z; a0.w += b0.w;
        a1.x += b1.x; a1.y += b1.y; a1.z += b1.z; a1.w += b1.w;
    }
    const float4 vb0 = *reinterpret_cast<const float4 *>(&bias[n0 + c]);
    const float4 vb1 = *reinterpret_cast<const float4 *>(&bias[n0 + c + 4]);
    const float o0 = tanhf(a0.x + vb0.x), o1 = tanhf(a0.y + vb0.y);
    const float o2 = tanhf(a0.z + vb0.z), o3 = tanhf(a0.w + vb0.w);
    const float o4 = tanhf(a1.x + vb1.x), o5 = tanhf(a1.y + vb1.y);
    const float o6 = tanhf(a1.z + vb1.z), o7 = tanhf(a1.w + vb1.w);
    __nv_bfloat16 h0, l0, h1, l1;
    const long base = (long)(m0 + row) * Hd + n0 + c;
    __nv_bfloat162 *oh = reinterpret_cast<__nv_bfloat162 *>(&dh[base]);
    __nv_bfloat162 *ol = reinterpret_cast<__nv_bfloat162 *>(&dl[base]);
    split_bf16(o0, h0, l0); split_bf16(o1, h1, l1);
    oh[0] = __halves2bfloat162(h0, h1); ol[0] = __halves2bfloat162(l0, l1);
    split_bf16(o2, h0, l0); split_bf16(o3, h1, l1);
    oh[1] = __halves2bfloat162(h0, h1); ol[1] = __halves2bfloat162(l0, l1);
    split_bf16(o4, h0, l0); split_bf16(o5, h1, l1);
    oh[2] = __halves2bfloat162(h0, h1); ol[2] = __halves2bfloat162(l0, l1);
    split_bf16(o6, h0, l0); split_bf16(o7, h1, l1);
    oh[3] = __halves2bfloat162(h0, h1); ol[3] = __halves2bfloat162(l0, l1);
}

__device__ __forceinline__ void convert_split(
    const float *__restrict__ s, __nv_bfloat16 *dh, __nv_bfloat16 *dl, int n, int gtid)
{
    for (int i = gtid; i < n; i += NCTA * NTHR) split_bf16(s[i], dh[i], dl[i]);
}

// Final-GEMM epilogue: out[:, s, :] tile = acc + fc_b (R8).
__device__ __forceinline__ void final_store(
    const float (&acc)[4][4][4], float *__restrict__ out,
    const float *__restrict__ fc_b, int s, int m0, int n0)
{
    const int lid = threadIdx.x & 31, wid = threadIdx.x >> 5;
    const int wm = wid >> 2, wn = wid & 3;
    const int g = lid >> 2, t = lid & 3;
#pragma unroll
    for (int ma = 0; ma < 4; ++ma)
#pragma unroll
        for (int na = 0; na < 4; ++na) {
            const int row = m0 + wm * 64 + ma * 16 + g;
            const int col = n0 + wn * 32 + na * 8 + t * 2;
            const float bx = fc_b[col], by = fc_b[col + 1];
            *reinterpret_cast<float2 *>(
                &out[(long)row * (Tt * Ind) + (long)s * Ind + col]) =
                make_float2(acc[ma][na][0] + bx, acc[ma][na][1] + by);
            *reinterpret_cast<float2 *>(
                &out[(long)(row + 8) * (Tt * Ind) + (long)s * Ind + col]) =
                make_float2(acc[ma][na][2] + bx, acc[ma][na][3] + by);
        }
}

// M0 dump with global coords (phase 0b only; ldc = Hd).
__device__ __forceinline__ void dump_glob(
    const float (&acc)[4][4][4], float *__restrict__ dst, int m0, int n0)
{
    const int lid = threadIdx.x & 31, wid = threadIdx.x >> 5;
    const int wm = wid >> 2, wn = wid & 3;
    const int g = lid >> 2, t = lid & 3;
#pragma unroll
    for (int ma = 0; ma < 4; ++ma)
#pragma unroll
        for (int na = 0; na < 4; ++na) {
            const int row = m0 + wm * 64 + ma * 16 + g;
            const int col = n0 + wn * 32 + na * 8 + t * 2;
            *reinterpret_cast<float2 *>(&dst[(long)row * Hd + col]) =
                make_float2(acc[ma][na][0], acc[ma][na][1]);
            *reinterpret_cast<float2 *>(&dst[(long)(row + 8) * Hd + col]) =
                make_float2(acc[ma][na][2], acc[ma][na][3]);
        }
}

__global__ void __launch_bounds__(NTHR, 1) rnn_tc(
    const float *__restrict__ y0,
    const float *__restrict__ W_ih0, const float *__restrict__ W_hh0,
    const float *__restrict__ b_ih0, const float *__restrict__ b_hh0,
    const float *__restrict__ W_ih1, const float *__restrict__ W_hh1,
    const float *__restrict__ b_ih1, const float *__restrict__ b_hh1,
    const float *__restrict__ fc_W, const float *__restrict__ fc_b,
    float *__restrict__ out)
{
    extern __shared__ char smem[];
    const u32 sb = smem_u32(smem);
    const int tid = threadIdx.x, bid = blockIdx.x;
    const int gtid = bid * NTHR + tid;
    const int stride = NCTA * NTHR;

    // ---- phase 0a (every replay): splits, transpose, init, biases, counters
    convert_split(W_ih0, g_Wih0h, g_Wih0l, Hd * Ind, gtid);
    convert_split(W_hh0, g_Whh0h, g_Whh0l, Hd * Hd, gtid);
    convert_split(W_ih1, g_Wih1h, g_Wih1l, Hd * Hd, gtid);
    convert_split(W_hh1, g_Whh1h, g_Whh1l, Hd * Hd, gtid);
    convert_split(fc_W, g_fcWh, g_fcWl, Ind * Hd, gtid);
    for (int i = gtid; i < Hd * Ind; i += stride) {  // fcWT[j][k] = fc_W[k][j]
        const int j = i >> 8, k = i & 255;
        split_bf16(fc_W[(long)k * Hd + j], g_fcWTh[i], g_fcWTl[i]);
    }
    for (int i = gtid; i < Bm * Ind; i += stride) {
        const float v = y0[i];
        split_bf16(v, g_yh[i], g_yl[i]);
        out[(long)(i >> 8) * (Tt * Ind) + (i & 255)] = v;  // out[:, 0, :]
    }
    for (int i = gtid; i < BmHd; i += stride) {
        const __nv_bfloat16 z = __float2bfloat16(0.0f);
        g_h0h[0][i] = z; g_h0l[0][i] = z;
        g_H1h[i] = z;    g_H1l[i] = z;   // history slot 0 = h1 initial state
    }
    for (int j = gtid; j < Hd; j += stride) {
        const float s1 = b_ih0[j] + b_hh0[j];
        g_biasA1[j] = s1;
        float a = 0.0f;
        const float *wr = &W_ih0[(long)j * Ind];
        for (int k = 0; k < Ind; ++k) a += wr[k] * fc_b[k];
        g_biasAf[j] = a + s1;              // fc_b @ W_ih0^T + b_ih0 + b_hh0
        g_biasB[j] = b_ih1[j] + b_hh1[j];
    }
    if (gtid < 16) g_tcnt[gtid] = 0;       // reset tile counters each replay
    grid_sync();

    // ---- phase 0b: M0 = W_ih0 @ fc_W  (1024x1024, K=256), 64 tiles x 2 k-splits
    {
        const int kk = bid >> 6, tj = bid & 63, tm = tj >> 3, tn = tj & 7;
        float acc[4][4][4] = {};
        gemm_pipe(acc, sb,
                  g_Wih0h + (long)tm * 128 * Ind, g_Wih0l + (long)tm * 128 * Ind, Ind,
                  g_fcWTh + (long)tn * 128 * Ind, g_fcWTl + (long)tn * 128 * Ind, Ind,
                  kk * 128, 2);
        dump_glob(acc, &g_part[0] + (long)kk * Hd * Hd, tm * 128, tn * 128);
    }
    grid_sync();
    {   // M0 reduce + split to bf16 hi/lo
        const float *p0 = &g_part[0];
        const float *p1 = p0 + (long)Hd * Hd;
        for (int i = gtid * 4; i < Hd * Hd; i += stride * 4) {
            const float4 a = __ldcg(reinterpret_cast<const float4 *>(&p0[i]));
            const float4 b = __ldcg(reinterpret_cast<const float4 *>(&p1[i]));
            split_bf16(a.x + b.x, g_M0h[i], g_M0l[i]);
            split_bf16(a.y + b.y, g_M0h[i + 1], g_M0l[i + 1]);
            split_bf16(a.z + b.z, g_M0h[i + 2], g_M0l[i + 2]);
            split_bf16(a.w + b.w, g_M0h[i + 3], g_M0l[i + 3]);
        }
    }
    grid_sync();

    // tile mapping (R8): 8 k-splits x (2m x 8n) over [256, 1024]
    const int ksAB = bid >> 4;
    const int tile = bid & 15;
    const int m0AB = ((bid >> 3) & 1) * 128, n0AB = (bid & 7) * 128;
    float *tbase = g_part + (long)tile * 8 * TILE_F;
    float *mypart = tbase + ksAB * TILE_F;
    u32 expv = 0;  // per-tile expected arrival count (monotonic)

    for (int s = 1; s < Tt; ++s) {
        const int cb = (s - 1) & 1, nb = s & 1;
        const __nv_bfloat16 *h1ph = g_H1h + (long)(s - 1) * BmHd;
        const __nv_bfloat16 *h1pl = g_H1l + (long)(s - 1) * BmHd;

        // ---- stage A: h0(s) = tanh(h1(s-1)@M0^T + h0(s-1)@Whh0^T + biasAf)
        {
            const int nprod = (s == 1) ? 4 : 8;
            const bool iproduce = (s == 1) ? (ksAB < 4) : true;
            if (iproduce) {
                float acc[4][4][4] = {};
                if (ksAB < 4) {
                    if (s == 1)
                        gemm_pipe(acc, sb,
                                  g_yh + (long)m0AB * Ind, g_yl + (long)m0AB * Ind, Ind,
                                  g_Wih0h + (long)n0AB * Ind, g_Wih0l + (long)n0AB * Ind, Ind,
                                  ksAB * 64, 1);
                    else
                        gemm_pipe(acc, sb,
                                  h1ph + (long)m0AB * Hd, h1pl + (long)m0AB * Hd, Hd,
                                  g_M0h + (long)n0AB * Hd, g_M0l + (long)n0AB * Hd, Hd,
                                  ksAB * 256, 4);
                } else {
                    gemm_pipe(acc, sb,
                              g_h0h[cb] + (long)m0AB * Hd, g_h0l[cb] + (long)m0AB * Hd, Hd,
                              g_Whh0h + (long)n0AB * Hd, g_Whh0l + (long)n0AB * Hd, Hd,
                              (ksAB - 4) * 256, 4);
                }
                dump_loc(acc, mypart);
            }
            expv += (u32)nprod;
            tile_sync(tile, iproduce, expv);
            merge_h(tbase, ksAB, nprod, s == 1 ? g_biasA1 : g_biasAf,
                    m0AB, n0AB, g_h0h[nb], g_h0l[nb]);
        }
        grid_sync();

        // ---- stage B: h1(s) = tanh(h0(s)@Wih1^T + h1(s-1)@Whh1^T + biasB)
        {
            float acc[4][4][4] = {};
            if (ksAB < 4)
                gemm_pipe(acc, sb,
                          g_h0h[nb] + (long)m0AB * Hd, g_h0l[nb] + (long)m0AB * Hd, Hd,
                          g_Wih1h + (long)n0AB * Hd, g_Wih1l + (long)n0AB * Hd, Hd,
                          ksAB * 256, 4);
            else
                gemm_pipe(acc, sb,
                          h1ph + (long)m0AB * Hd, h1pl + (long)m0AB * Hd, Hd,
                          g_Whh1h + (long)n0AB * Hd, g_Whh1l + (long)n0AB * Hd, Hd,
                          (ksAB - 4) * 256, 4);
            dump_loc(acc, mypart);
            expv += 8u;
            tile_sync(tile, true, expv);
            merge_h(tbase, ksAB, 8, g_biasB, m0AB, n0AB,
                    g_H1h + (long)s * BmHd, g_H1l + (long)s * BmHd);
        }
        grid_sync();
    }

    // ---- batched output GEMM: out[:, s, :] = H1[s] @ fc_W^T + fc_b, s = 1..511
    for (int job = bid; job < (Tt - 1) * 4; job += NCTA) {
        const int ntile = job & 1;
        const int rt = job >> 1;
        const int s = 1 + (rt >> 1);
        const int m0 = (rt & 1) * 128, n0 = ntile * 128;
        float acc[4][4][4] = {};
        gemm_pipe(acc, sb,
                  g_H1h + (long)s * BmHd + (long)m0 * Hd,
                  g_H1l + (long)s * BmHd + (long)m0 * Hd, Hd,
                  g_fcWh + (long)n0 * Hd, g_fcWl + (long)n0 * Hd, Hd,
                  0, 16);
        final_store(acc, out, fc_b, s, m0, n0);
    }
}

extern "C" void kernel_launch(void *const *d_in, const int *in_sizes, int n_in,
                              void *d_out, int out_size) {
    (void)in_sizes; (void)n_in; (void)out_size;
    const float *y0    = (const float *)d_in[0];
    // d_in[1] = t (length only; unused)
    const float *W_ih0 = (const float *)d_in[2];
    const float *W_hh0 = (const float *)d_in[3];
    const float *b_ih0 = (const float *)d_in[4];
    const float *b_hh0 = (const float *)d_in[5];
    const float *W_ih1 = (const float *)d_in[6];
    const float *W_hh1 = (const float *)d_in[7];
    const float *b_ih1 = (const float *)d_in[8];
    const float *b_hh1 = (const float *)d_in[9];
    const float *fc_W  = (const float *)d_in[10];
    const float *fc_b  = (const float *)d_in[11];
    float *out = (float *)d_out;

    cudaFuncSetAttribute(rnn_tc, cudaFuncAttributeMaxDynamicSharedMemorySize, SMEM_BYTES);
    rnn_tc<<<NCTA, NTHR, SMEM_BYTES>>>(y0, W_ih0, W_hh0, b_ih0, b_hh0,
                                       W_ih1, W_hh1, b_ih1, b_hh1,
                                       fc_W, fc_b, out);
}